// round 11
// baseline (speedup 1.0000x reference)
#include <cuda_runtime.h>
#include <cuda_fp16.h>

#define NTOK 16384
#define NEXP 64
#define DIM  2048
#define KCH  64                    // original k per chunk
#define NCHUNK (DIM / KCH)         // 32
#define TOKB 64
#define THREADS 256
#define ROWH 72                    // padded row: 72 halfs = 144B
#define SPLITB (64 * ROWH * 2)     // 9216 B per split tile
#define BUFB   (2 * SPLITB)        // 18432 B per buffer (2 splits)
// dynamic smem: X 3 bufs, W 3 bufs, bias
#define XOFF 0
#define WOFF (3 * BUFB)            // 55296
#define BOFF (6 * BUFB)            // 110592
#define SMTOT (BOFF + 256)         // 110848
#define INV256 0.00390625f

typedef unsigned long long ull;

// W pre-scaled x256, fp16 2-split, padded: gW[c][split][exp][ROWH]
__device__ __align__(16) __half gW[NCHUNK * 2 * NEXP * ROWH];

// ---------- helpers ----------
__device__ __forceinline__ unsigned smem_u32(const void* p) {
    unsigned a;
    asm("{ .reg .u64 t; cvta.to.shared.u64 t, %1; cvt.u32.u64 %0, t; }" : "=r"(a) : "l"(p));
    return a;
}
__device__ __forceinline__ void cpasync16(unsigned s, const void* g) {
    asm volatile("cp.async.cg.shared.global [%0], [%1], 16;" :: "r"(s), "l"(g));
}
__device__ __forceinline__ void ldm4(unsigned* r, unsigned addr) {
    asm volatile("ldmatrix.sync.aligned.m8n8.x4.shared.b16 {%0,%1,%2,%3}, [%4];"
                 : "=r"(r[0]), "=r"(r[1]), "=r"(r[2]), "=r"(r[3]) : "r"(addr));
}
__device__ __forceinline__ void mma16816(float* d, const unsigned* a, const unsigned* b) {
    asm volatile("mma.sync.aligned.m16n8k16.row.col.f32.f16.f16.f32 "
                 "{%0,%1,%2,%3}, {%4,%5,%6,%7}, {%8,%9}, {%0,%1,%2,%3};"
                 : "+f"(d[0]), "+f"(d[1]), "+f"(d[2]), "+f"(d[3])
                 : "r"(a[0]), "r"(a[1]), "r"(a[2]), "r"(a[3]), "r"(b[0]), "r"(b[1]));
}

// ---------- kernel 1: scale + split + pad W ----------
__global__ void prep_W(const float* __restrict__ W) {
    int i = blockIdx.x * blockDim.x + threadIdx.x;
    if (i >= NEXP * DIM) return;
    int e = i >> 11, k = i & (DIM - 1);
    int c = k >> 6, kin = k & 63;
    float x = W[i] * 256.0f;
    __half h = __float2half_rn(x);
    float r = x - __half2float(h);
    __half m = __float2half_rn(r);
    gW[((c * 2 + 0) * NEXP + e) * ROWH + kin] = h;
    gW[((c * 2 + 1) * NEXP + e) * ROWH + kin] = m;
}

// ---------- kernel 2: fp16 2-split HMMA GEMM, staging interleaved into MMA stream ----------
__global__ __launch_bounds__(THREADS, 2)
void gate_hmma(const float* __restrict__ inp,
               const float* __restrict__ bias,
               float* __restrict__ out,
               int out_size) {
    extern __shared__ __align__(16) char smem[];
    const unsigned SB = smem_u32(smem);
    const unsigned XD = SB + XOFF;
    const unsigned WD = SB + WOFF;
    float* bsm = (float*)(smem + BOFF);

    const int tid  = threadIdx.x;
    const int wid  = tid >> 5;
    const int lane = tid & 31;
    const int tg   = wid & 1;        // token group
    const int kq   = wid >> 1;       // K quarter of each 64-k chunk
    const int tokBase = blockIdx.x * TOKB;

    if (tid < 64) bsm[tid] = bias[tid];

    const int xTok = tid >> 2;
    const int xq   = tid & 3;

    const unsigned aConst = (unsigned)((tg * 32 + (lane & 15)) * 144 + kq * 32 + ((lane >> 4) << 4));
    const unsigned bConst = (unsigned)(((lane & 7) + ((lane >> 4) << 3)) * 144 + kq * 32 + (((lane >> 3) & 1) << 4));

    float d0[8][4], d1[8][4];
#pragma unroll
    for (int j = 0; j < 8; j++)
#pragma unroll
        for (int q = 0; q < 4; q++) { d0[j][q] = 0.f; d1[j][q] = 0.f; }

    // ---- staging helpers ----
    auto stageW = [&](int c, int b) {
        const char* ws = (const char*)gW + (size_t)c * BUFB;
        unsigned wd = WD + b * BUFB;
#pragma unroll
        for (int j = 0; j < 5; j++) {
            int o = tid + j * 256;
            if (o < BUFB / 16) cpasync16(wd + o * 16, ws + o * 16);
        }
    };
    auto ldgX = [&](int c, float4* v) {
        const float4* xs = (const float4*)(inp + (size_t)(tokBase + xTok) * DIM + c * KCH + xq * 16);
        v[0] = xs[0]; v[1] = xs[1]; v[2] = xs[2]; v[3] = xs[3];
    };
    auto stsX = [&](const float4* v, int b) {
        float xv[16] = {v[0].x,v[0].y,v[0].z,v[0].w, v[1].x,v[1].y,v[1].z,v[1].w,
                        v[2].x,v[2].y,v[2].z,v[2].w, v[3].x,v[3].y,v[3].z,v[3].w};
        unsigned hw[8], mw[8];
#pragma unroll
        for (int i = 0; i < 8; i++) {
            __half2 h2 = __floats2half2_rn(xv[2*i], xv[2*i+1]);
            float2 hf = __half22float2(h2);
            __half2 m2 = __floats2half2_rn(xv[2*i] - hf.x, xv[2*i+1] - hf.y);
            hw[i] = *(unsigned*)&h2;
            mw[i] = *(unsigned*)&m2;
        }
        char* xh = smem + XOFF + b * BUFB + xTok * 144 + xq * 32;
        ((uint4*)xh)[0] = make_uint4(hw[0], hw[1], hw[2], hw[3]);
        ((uint4*)xh)[1] = make_uint4(hw[4], hw[5], hw[6], hw[7]);
        char* xm = xh + SPLITB;
        ((uint4*)xm)[0] = make_uint4(mw[0], mw[1], mw[2], mw[3]);
        ((uint4*)xm)[1] = make_uint4(mw[4], mw[5], mw[6], mw[7]);
    };

    // ---- prologue ----
    float4 xr[4];
    stageW(0, 0);
    asm volatile("cp.async.commit_group;");
    ldgX(0, xr);
    stsX(xr, 0);          // X chunk 0 -> buf 0
    ldgX(1, xr);          // X chunk 1 held in regs

    for (int c = 0; c < NCHUNK; c++) {
        const int b3 = c % 3;
        // issue W(c+1) fetch first: full chunk to land
        if (c + 1 < NCHUNK) stageW(c + 1, (c + 1) % 3);
        asm volatile("cp.async.commit_group;");
        if (c + 1 < NCHUNK) asm volatile("cp.async.wait_group 1;");   // W(c) landed
        else                asm volatile("cp.async.wait_group 0;");
        __syncthreads();

        // ---- compute chunk c, staging interleaved after g1 ----
        const unsigned xA = XD + b3 * BUFB + aConst;
        const unsigned wA = WD + b3 * BUFB + bConst;
        unsigned ah0[4], ah1[4], am0[4], am1[4];
        ldm4(ah0, xA);
        ldm4(ah1, xA + 2304);
        ldm4(am0, xA + SPLITB);
        ldm4(am1, xA + SPLITB + 2304);

        unsigned bh[4], bm[4], bh2[4], bm2[4];
        // g = 0
        ldm4(bh, wA);
        ldm4(bm, wA + SPLITB);
        mma16816(d0[0], ah0, bh);   mma16816(d0[1], ah0, bh + 2);
        mma16816(d1[0], ah1, bh);   mma16816(d1[1], ah1, bh + 2);
        mma16816(d0[0], ah0, bm);   mma16816(d0[1], ah0, bm + 2);
        mma16816(d1[0], ah1, bm);   mma16816(d1[1], ah1, bm + 2);
        mma16816(d0[0], am0, bh);   mma16816(d0[1], am0, bh + 2);
        mma16816(d1[0], am1, bh);   mma16816(d1[1], am1, bh + 2);
        // g = 1
        ldm4(bh2, wA + 2304);
        ldm4(bm2, wA + SPLITB + 2304);
        mma16816(d0[2], ah0, bh2);  mma16816(d0[3], ah0, bh2 + 2);
        mma16816(d1[2], ah1, bh2);  mma16816(d1[3], ah1, bh2 + 2);
        mma16816(d0[2], ah0, bm2);  mma16816(d0[3], ah0, bm2 + 2);
        mma16816(d1[2], ah1, bm2);  mma16816(d1[3], ah1, bm2 + 2);
        mma16816(d0[2], am0, bh2);  mma16816(d0[3], am0, bh2 + 2);
        mma16816(d1[2], am1, bh2);  mma16816(d1[3], am1, bh2 + 2);

        // pre-issue g2 B loads so their latency hides under the staging blob
        ldm4(bh, wA + 2 * 2304);
        ldm4(bm, wA + SPLITB + 2 * 2304);

        // ---- mid-compute staging: overlaps with queued MMAs across warps ----
        if (c + 1 < NCHUNK) stsX(xr, (c + 1) % 3);   // X(c+1) from held regs
        if (c + 2 < NCHUNK) ldgX(c + 2, xr);         // X(c+2) into regs

        // g = 2
        mma16816(d0[4], ah0, bh);   mma16816(d0[5], ah0, bh + 2);
        mma16816(d1[4], ah1, bh);   mma16816(d1[5], ah1, bh + 2);
        mma16816(d0[4], ah0, bm);   mma16816(d0[5], ah0, bm + 2);
        mma16816(d1[4], ah1, bm);   mma16816(d1[5], ah1, bm + 2);
        mma16816(d0[4], am0, bh);   mma16816(d0[5], am0, bh + 2);
        mma16816(d1[4], am1, bh);   mma16816(d1[5], am1, bh + 2);
        // g = 3
        ldm4(bh2, wA + 3 * 2304);
        ldm4(bm2, wA + SPLITB + 3 * 2304);
        mma16816(d0[6], ah0, bh2);  mma16816(d0[7], ah0, bh2 + 2);
        mma16816(d1[6], ah1, bh2);  mma16816(d1[7], ah1, bh2 + 2);
        mma16816(d0[6], ah0, bm2);  mma16816(d0[7], ah0, bm2 + 2);
        mma16816(d1[6], ah1, bm2);  mma16816(d1[7], ah1, bm2 + 2);
        mma16816(d0[6], am0, bh2);  mma16816(d0[7], am0, bh2 + 2);
        mma16816(d1[6], am1, bh2);  mma16816(d1[7], am1, bh2 + 2);
    }
    __syncthreads();   // all compute done before scratch reuse

    // ---- reduce across the 4 K-quarter crews (scratch reuses staging smem) ----
    float* scr = (float*)smem;   // rows of 68 floats (272B)

    if (kq >= 2) {
        int row = (tg * 2 + (kq - 2)) * 32 + lane;
#pragma unroll
        for (int j = 0; j < 8; j++)
            *(float4*)(scr + row * 68 + j * 4) = make_float4(d0[j][0], d0[j][1], d0[j][2], d0[j][3]);
#pragma unroll
        for (int j = 0; j < 8; j++)
            *(float4*)(scr + row * 68 + 32 + j * 4) = make_float4(d1[j][0], d1[j][1], d1[j][2], d1[j][3]);
    }
    __syncthreads();
    if (kq < 2) {
        int row = (tg * 2 + kq) * 32 + lane;
#pragma unroll
        for (int j = 0; j < 8; j++) {
            float4 v = *(const float4*)(scr + row * 68 + j * 4);
            d0[j][0] += v.x; d0[j][1] += v.y; d0[j][2] += v.z; d0[j][3] += v.w;
        }
#pragma unroll
        for (int j = 0; j < 8; j++) {
            float4 v = *(const float4*)(scr + row * 68 + 32 + j * 4);
            d1[j][0] += v.x; d1[j][1] += v.y; d1[j][2] += v.z; d1[j][3] += v.w;
        }
    }
    __syncthreads();
    if (kq == 1) {
        int row = tg * 32 + lane;
#pragma unroll
        for (int j = 0; j < 8; j++)
            *(float4*)(scr + row * 68 + j * 4) = make_float4(d0[j][0], d0[j][1], d0[j][2], d0[j][3]);
#pragma unroll
        for (int j = 0; j < 8; j++)
            *(float4*)(scr + row * 68 + 32 + j * 4) = make_float4(d1[j][0], d1[j][1], d1[j][2], d1[j][3]);
    }
    __syncthreads();

    if (kq == 0) {
        int row = tg * 32 + lane;
#pragma unroll
        for (int j = 0; j < 8; j++) {
            float4 v = *(const float4*)(scr + row * 68 + j * 4);
            d0[j][0] += v.x; d0[j][1] += v.y; d0[j][2] += v.z; d0[j][3] += v.w;
        }
#pragma unroll
        for (int j = 0; j < 8; j++) {
            float4 v = *(const float4*)(scr + row * 68 + 32 + j * 4);
            d1[j][0] += v.x; d1[j][1] += v.y; d1[j][2] += v.z; d1[j][3] += v.w;
        }

        // ---- epilogue: unscale, +bias, top-2 over 64, softmax ----
        const int half = out_size >> 1;
#pragma unroll
        for (int mt = 0; mt < 2; mt++) {
#pragma unroll
            for (int rh = 0; rh < 2; rh++) {
                float v0 = -3.4e38f, v1 = -3.4e38f;
                int   i0 = -1,       i1 = -1;
#pragma unroll
                for (int j = 0; j < 8; j++) {
#pragma unroll
                    for (int v = 0; v < 2; v++) {
                        int e = j * 8 + (lane & 3) * 2 + v;
                        float dv = (mt == 0) ? d0[j][rh * 2 + v] : d1[j][rh * 2 + v];
                        float f = dv * INV256 + bsm[e];
                        if (f > v0)      { v1 = v0; i1 = i0; v0 = f; i0 = e; }
                        else if (f > v1) { v1 = f;  i1 = e; }
                    }
                }
#pragma unroll
                for (int ofs = 1; ofs < 4; ofs <<= 1) {
                    float u0 = __shfl_xor_sync(0xFFFFFFFFu, v0, ofs);
                    float u1 = __shfl_xor_sync(0xFFFFFFFFu, v1, ofs);
                    int   j0 = __shfl_xor_sync(0xFFFFFFFFu, i0, ofs);
                    int   j1 = __shfl_xor_sync(0xFFFFFFFFu, i1, ofs);
                    bool afirst = (v0 > u0) || (v0 == u0 && i0 < j0);
                    float nv0, nv1; int ni0, ni1;
                    if (afirst) {
                        nv0 = v0; ni0 = i0;
                        bool s = (u0 > v1) || (u0 == v1 && j0 < i1);
                        nv1 = s ? u0 : v1; ni1 = s ? j0 : i1;
                    } else {
                        nv0 = u0; ni0 = j0;
                        bool s = (v0 > u1) || (v0 == u1 && i0 < j1);
                        nv1 = s ? v0 : u1; ni1 = s ? i0 : j1;
                    }
                    v0 = nv0; v1 = nv1; i0 = ni0; i1 = ni1;
                }
                if ((lane & 3) == 0) {
                    int tok = tokBase + tg * 32 + mt * 16 + rh * 8 + (lane >> 2);
                    float ex = expf(v1 - v0);
                    float s0 = 1.0f / (1.0f + ex);
                    float s1 = ex * s0;
                    out[tok * 2 + 0] = (float)i0;
                    out[tok * 2 + 1] = (float)i1;
                    out[half + tok * 2 + 0] = s0;
                    out[half + tok * 2 + 1] = s1;
                }
            }
        }
    }
}

extern "C" void kernel_launch(void* const* d_in, const int* in_sizes, int n_in,
                              void* d_out, int out_size) {
    const float* inp  = (const float*)d_in[0];   // [16384, 2048]
    const float* W    = (const float*)d_in[1];   // [64, 2048]
    const float* bias = (const float*)d_in[2];   // [64]
    float* out = (float*)d_out;

    cudaFuncSetAttribute(gate_hmma, cudaFuncAttributeMaxDynamicSharedMemorySize, SMTOT);
    prep_W<<<(NEXP * DIM + 255) / 256, 256>>>(W);
    gate_hmma<<<NTOK / TOKB, THREADS, SMTOT>>>(inp, bias, out, out_size);
}

// round 12
// speedup vs baseline: 1.1486x; 1.1486x over previous
#include <cuda_runtime.h>
#include <cuda_fp16.h>

#define NTOK 16384
#define NEXP 64
#define DIM  2048
#define KCH  64                    // original k per chunk
#define NCHUNK (DIM / KCH)         // 32
#define TOKB 64
#define THREADS 256
#define ROWH 72                    // padded row: 72 halfs = 144B
#define SPLITB (64 * ROWH * 2)     // 9216 B per split tile
#define BUFB   (2 * SPLITB)        // 18432 B per buffer (2 splits)
// dynamic smem: X 3 bufs, W 3 bufs, bias
#define XOFF 0
#define WOFF (3 * BUFB)            // 55296
#define BOFF (6 * BUFB)            // 110592
#define SMTOT (BOFF + 256)         // 110848
#define INV256 0.00390625f

typedef unsigned long long ull;

// W pre-scaled x256, fp16 2-split, padded: gW[c][split][exp][ROWH]
__device__ __align__(16) __half gW[NCHUNK * 2 * NEXP * ROWH];

// ---------- helpers ----------
__device__ __forceinline__ unsigned smem_u32(const void* p) {
    unsigned a;
    asm("{ .reg .u64 t; cvta.to.shared.u64 t, %1; cvt.u32.u64 %0, t; }" : "=r"(a) : "l"(p));
    return a;
}
__device__ __forceinline__ void cpasync16(unsigned s, const void* g) {
    asm volatile("cp.async.cg.shared.global [%0], [%1], 16;" :: "r"(s), "l"(g));
}
__device__ __forceinline__ void ldm4(unsigned* r, unsigned addr) {
    asm volatile("ldmatrix.sync.aligned.m8n8.x4.shared.b16 {%0,%1,%2,%3}, [%4];"
                 : "=r"(r[0]), "=r"(r[1]), "=r"(r[2]), "=r"(r[3]) : "r"(addr));
}
__device__ __forceinline__ void mma16816(float* d, const unsigned* a, const unsigned* b) {
    asm volatile("mma.sync.aligned.m16n8k16.row.col.f32.f16.f16.f32 "
                 "{%0,%1,%2,%3}, {%4,%5,%6,%7}, {%8,%9}, {%0,%1,%2,%3};"
                 : "+f"(d[0]), "+f"(d[1]), "+f"(d[2]), "+f"(d[3])
                 : "r"(a[0]), "r"(a[1]), "r"(a[2]), "r"(a[3]), "r"(b[0]), "r"(b[1]));
}

// ---------- kernel 1: scale + split + pad W ----------
__global__ void prep_W(const float* __restrict__ W) {
    int i = blockIdx.x * blockDim.x + threadIdx.x;
    if (i >= NEXP * DIM) return;
    int e = i >> 11, k = i & (DIM - 1);
    int c = k >> 6, kin = k & 63;
    float x = W[i] * 256.0f;
    __half h = __float2half_rn(x);
    float r = x - __half2float(h);
    __half m = __float2half_rn(r);
    gW[((c * 2 + 0) * NEXP + e) * ROWH + kin] = h;
    gW[((c * 2 + 1) * NEXP + e) * ROWH + kin] = m;
}

// ---------- kernel 2: fp16 2-split HMMA GEMM, wave-ordered MMAs ----------
__global__ __launch_bounds__(THREADS, 2)
void gate_hmma(const float* __restrict__ inp,
               const float* __restrict__ bias,
               float* __restrict__ out,
               int out_size) {
    extern __shared__ __align__(16) char smem[];
    const unsigned SB = smem_u32(smem);
    const unsigned XD = SB + XOFF;
    const unsigned WD = SB + WOFF;
    float* bsm = (float*)(smem + BOFF);

    const int tid  = threadIdx.x;
    const int wid  = tid >> 5;
    const int lane = tid & 31;
    const int tg   = wid & 1;        // token group
    const int kq   = wid >> 1;       // K quarter of each 64-k chunk
    const int tokBase = blockIdx.x * TOKB;

    if (tid < 64) bsm[tid] = bias[tid];

    const int xTok = tid >> 2;
    const int xq   = tid & 3;

    const unsigned aConst = (unsigned)((tg * 32 + (lane & 15)) * 144 + kq * 32 + ((lane >> 4) << 4));
    const unsigned bConst = (unsigned)(((lane & 7) + ((lane >> 4) << 3)) * 144 + kq * 32 + (((lane >> 3) & 1) << 4));

    float d0[8][4], d1[8][4];
#pragma unroll
    for (int j = 0; j < 8; j++)
#pragma unroll
        for (int q = 0; q < 4; q++) { d0[j][q] = 0.f; d1[j][q] = 0.f; }

    // ---- staging helpers ----
    auto stageW = [&](int c, int b) {
        const char* ws = (const char*)gW + (size_t)c * BUFB;
        unsigned wd = WD + b * BUFB;
#pragma unroll
        for (int j = 0; j < 5; j++) {
            int o = tid + j * 256;
            if (o < BUFB / 16) cpasync16(wd + o * 16, ws + o * 16);
        }
    };
    auto ldgX = [&](int c, float4* v) {
        const float4* xs = (const float4*)(inp + (size_t)(tokBase + xTok) * DIM + c * KCH + xq * 16);
        v[0] = xs[0]; v[1] = xs[1]; v[2] = xs[2]; v[3] = xs[3];
    };
    auto stsX = [&](const float4* v, int b) {
        float xv[16] = {v[0].x,v[0].y,v[0].z,v[0].w, v[1].x,v[1].y,v[1].z,v[1].w,
                        v[2].x,v[2].y,v[2].z,v[2].w, v[3].x,v[3].y,v[3].z,v[3].w};
        unsigned hw[8], mw[8];
#pragma unroll
        for (int i = 0; i < 8; i++) {
            __half2 h2 = __floats2half2_rn(xv[2*i], xv[2*i+1]);
            float2 hf = __half22float2(h2);
            __half2 m2 = __floats2half2_rn(xv[2*i] - hf.x, xv[2*i+1] - hf.y);
            hw[i] = *(unsigned*)&h2;
            mw[i] = *(unsigned*)&m2;
        }
        char* xh = smem + XOFF + b * BUFB + xTok * 144 + xq * 32;
        ((uint4*)xh)[0] = make_uint4(hw[0], hw[1], hw[2], hw[3]);
        ((uint4*)xh)[1] = make_uint4(hw[4], hw[5], hw[6], hw[7]);
        char* xm = xh + SPLITB;
        ((uint4*)xm)[0] = make_uint4(mw[0], mw[1], mw[2], mw[3]);
        ((uint4*)xm)[1] = make_uint4(mw[4], mw[5], mw[6], mw[7]);
    };

    // ---- prologue ----
    float4 xr[4];
    stageW(0, 0);
    asm volatile("cp.async.commit_group;");
    ldgX(0, xr);
    stsX(xr, 0);          // X chunk 0 -> buf 0
    ldgX(1, xr);          // X chunk 1 held in regs

    for (int c = 0; c < NCHUNK; c++) {
        const int b3 = c % 3;
        if (c + 1 < NCHUNK) {
            stageW(c + 1, (c + 1) % 3);
            asm volatile("cp.async.commit_group;");
            stsX(xr, (c + 1) % 3);                       // X(c+1); xr dead after this
            asm volatile("cp.async.wait_group 1;");      // W(c) landed
        } else {
            asm volatile("cp.async.commit_group;");
            asm volatile("cp.async.wait_group 0;");
        }
        __syncthreads();

        // ---- compute chunk c: load ALL frags, 3 waves of 16 independent MMAs ----
        {
            const unsigned xA = XD + b3 * BUFB + aConst;
            const unsigned wA = WD + b3 * BUFB + bConst;
            unsigned ah0[4], ah1[4], am0[4], am1[4];
            unsigned bh[4][4], bm[4][4];
            ldm4(ah0, xA);
            ldm4(ah1, xA + 2304);
            ldm4(am0, xA + SPLITB);
            ldm4(am1, xA + SPLITB + 2304);
#pragma unroll
            for (int g = 0; g < 4; g++) {
                ldm4(bh[g], wA + g * 2304);
                ldm4(bm[g], wA + SPLITB + g * 2304);
            }
            // wave 1: hh — 16 independent MMAs
#pragma unroll
            for (int g = 0; g < 4; g++) {
                mma16816(d0[2*g],   ah0, bh[g]);  mma16816(d0[2*g+1], ah0, bh[g] + 2);
                mma16816(d1[2*g],   ah1, bh[g]);  mma16816(d1[2*g+1], ah1, bh[g] + 2);
            }
            // wave 2: hm — chain link spaced 16 MMAs after wave 1
#pragma unroll
            for (int g = 0; g < 4; g++) {
                mma16816(d0[2*g],   ah0, bm[g]);  mma16816(d0[2*g+1], ah0, bm[g] + 2);
                mma16816(d1[2*g],   ah1, bm[g]);  mma16816(d1[2*g+1], ah1, bm[g] + 2);
            }
            // wave 3: mh
#pragma unroll
            for (int g = 0; g < 4; g++) {
                mma16816(d0[2*g],   am0, bh[g]);  mma16816(d0[2*g+1], am0, bh[g] + 2);
                mma16816(d1[2*g],   am1, bh[g]);  mma16816(d1[2*g+1], am1, bh[g] + 2);
            }
        }

        // X(c+2) load AFTER compute: xr live only across barrier, not the MMA stream
        if (c + 2 < NCHUNK) ldgX(c + 2, xr);
    }
    __syncthreads();   // all compute done before scratch reuse

    // ---- reduce across the 4 K-quarter crews (scratch reuses staging smem) ----
    float* scr = (float*)smem;   // rows of 68 floats (272B)

    if (kq >= 2) {
        int row = (tg * 2 + (kq - 2)) * 32 + lane;
#pragma unroll
        for (int j = 0; j < 8; j++)
            *(float4*)(scr + row * 68 + j * 4) = make_float4(d0[j][0], d0[j][1], d0[j][2], d0[j][3]);
#pragma unroll
        for (int j = 0; j < 8; j++)
            *(float4*)(scr + row * 68 + 32 + j * 4) = make_float4(d1[j][0], d1[j][1], d1[j][2], d1[j][3]);
    }
    __syncthreads();
    if (kq < 2) {
        int row = (tg * 2 + kq) * 32 + lane;
#pragma unroll
        for (int j = 0; j < 8; j++) {
            float4 v = *(const float4*)(scr + row * 68 + j * 4);
            d0[j][0] += v.x; d0[j][1] += v.y; d0[j][2] += v.z; d0[j][3] += v.w;
        }
#pragma unroll
        for (int j = 0; j < 8; j++) {
            float4 v = *(const float4*)(scr + row * 68 + 32 + j * 4);
            d1[j][0] += v.x; d1[j][1] += v.y; d1[j][2] += v.z; d1[j][3] += v.w;
        }
    }
    __syncthreads();
    if (kq == 1) {
        int row = tg * 32 + lane;
#pragma unroll
        for (int j = 0; j < 8; j++)
            *(float4*)(scr + row * 68 + j * 4) = make_float4(d0[j][0], d0[j][1], d0[j][2], d0[j][3]);
#pragma unroll
        for (int j = 0; j < 8; j++)
            *(float4*)(scr + row * 68 + 32 + j * 4) = make_float4(d1[j][0], d1[j][1], d1[j][2], d1[j][3]);
    }
    __syncthreads();

    if (kq == 0) {
        int row = tg * 32 + lane;
#pragma unroll
        for (int j = 0; j < 8; j++) {
            float4 v = *(const float4*)(scr + row * 68 + j * 4);
            d0[j][0] += v.x; d0[j][1] += v.y; d0[j][2] += v.z; d0[j][3] += v.w;
        }
#pragma unroll
        for (int j = 0; j < 8; j++) {
            float4 v = *(const float4*)(scr + row * 68 + 32 + j * 4);
            d1[j][0] += v.x; d1[j][1] += v.y; d1[j][2] += v.z; d1[j][3] += v.w;
        }

        // ---- epilogue: unscale, +bias, top-2 over 64, softmax ----
        const int half = out_size >> 1;
#pragma unroll
        for (int mt = 0; mt < 2; mt++) {
#pragma unroll
            for (int rh = 0; rh < 2; rh++) {
                float v0 = -3.4e38f, v1 = -3.4e38f;
                int   i0 = -1,       i1 = -1;
#pragma unroll
                for (int j = 0; j < 8; j++) {
#pragma unroll
                    for (int v = 0; v < 2; v++) {
                        int e = j * 8 + (lane & 3) * 2 + v;
                        float dv = (mt == 0) ? d0[j][rh * 2 + v] : d1[j][rh * 2 + v];
                        float f = dv * INV256 + bsm[e];
                        if (f > v0)      { v1 = v0; i1 = i0; v0 = f; i0 = e; }
                        else if (f > v1) { v1 = f;  i1 = e; }
                    }
                }
#pragma unroll
                for (int ofs = 1; ofs < 4; ofs <<= 1) {
                    float u0 = __shfl_xor_sync(0xFFFFFFFFu, v0, ofs);
                    float u1 = __shfl_xor_sync(0xFFFFFFFFu, v1, ofs);
                    int   j0 = __shfl_xor_sync(0xFFFFFFFFu, i0, ofs);
                    int   j1 = __shfl_xor_sync(0xFFFFFFFFu, i1, ofs);
                    bool afirst = (v0 > u0) || (v0 == u0 && i0 < j0);
                    float nv0, nv1; int ni0, ni1;
                    if (afirst) {
                        nv0 = v0; ni0 = i0;
                        bool s = (u0 > v1) || (u0 == v1 && j0 < i1);
                        nv1 = s ? u0 : v1; ni1 = s ? j0 : i1;
                    } else {
                        nv0 = u0; ni0 = j0;
                        bool s = (v0 > u1) || (v0 == u1 && i0 < j1);
                        nv1 = s ? v0 : u1; ni1 = s ? i0 : j1;
                    }
                    v0 = nv0; v1 = nv1; i0 = ni0; i1 = ni1;
                }
                if ((lane & 3) == 0) {
                    int tok = tokBase + tg * 32 + mt * 16 + rh * 8 + (lane >> 2);
                    float ex = expf(v1 - v0);
                    float s0 = 1.0f / (1.0f + ex);
                    float s1 = ex * s0;
                    out[tok * 2 + 0] = (float)i0;
                    out[tok * 2 + 1] = (float)i1;
                    out[half + tok * 2 + 0] = s0;
                    out[half + tok * 2 + 1] = s1;
                }
            }
        }
    }
}

extern "C" void kernel_launch(void* const* d_in, const int* in_sizes, int n_in,
                              void* d_out, int out_size) {
    const float* inp  = (const float*)d_in[0];   // [16384, 2048]
    const float* W    = (const float*)d_in[1];   // [64, 2048]
    const float* bias = (const float*)d_in[2];   // [64]
    float* out = (float*)d_out;

    cudaFuncSetAttribute(gate_hmma, cudaFuncAttributeMaxDynamicSharedMemorySize, SMTOT);
    prep_W<<<(NEXP * DIM + 255) / 256, 256>>>(W);
    gate_hmma<<<NTOK / TOKB, THREADS, SMTOT>>>(inp, bias, out, out_size);
}

// round 13
// speedup vs baseline: 1.2709x; 1.1065x over previous
#include <cuda_runtime.h>
#include <cuda_fp16.h>

#define NTOK 16384
#define NEXP 64
#define DIM  2048
#define KCH  64
#define NCHUNK (DIM / KCH)      // 32
#define TOKB 128
#define THREADS 512
#define ROWH 72                 // 144B rows (72 halfs)
#define XSPLITB (TOKB * 144)    // 18432 B per X split tile
#define XBUFB   (2 * XSPLITB)   // 36864 B per X buffer
#define WSPLITB (64 * 144)      // 9216 B per W split tile
#define WBUFB   (2 * WSPLITB)   // 18432 B per W buffer
// dynamic smem: X 2 bufs, W 2 bufs, bias
#define XOFF 0
#define WOFF (2 * XBUFB)        // 73728
#define BOFF (WOFF + 2 * WBUFB) // 110592
#define SMTOT (BOFF + 256)      // 110848
#define INV256 0.00390625f

typedef unsigned long long ull;

// W pre-scaled x256, fp16 2-split, padded: gW[c][split][exp][ROWH]  (18432B per chunk)
__device__ __align__(16) __half gW[NCHUNK * 2 * NEXP * ROWH];

// ---------- helpers ----------
__device__ __forceinline__ unsigned smem_u32(const void* p) {
    unsigned a;
    asm("{ .reg .u64 t; cvta.to.shared.u64 t, %1; cvt.u32.u64 %0, t; }" : "=r"(a) : "l"(p));
    return a;
}
__device__ __forceinline__ void cpasync16(unsigned s, const void* g) {
    asm volatile("cp.async.cg.shared.global [%0], [%1], 16;" :: "r"(s), "l"(g));
}
__device__ __forceinline__ void ldm4(unsigned* r, unsigned addr) {
    asm volatile("ldmatrix.sync.aligned.m8n8.x4.shared.b16 {%0,%1,%2,%3}, [%4];"
                 : "=r"(r[0]), "=r"(r[1]), "=r"(r[2]), "=r"(r[3]) : "r"(addr));
}
__device__ __forceinline__ void mma16816(float* d, const unsigned* a, const unsigned* b) {
    asm volatile("mma.sync.aligned.m16n8k16.row.col.f32.f16.f16.f32 "
                 "{%0,%1,%2,%3}, {%4,%5,%6,%7}, {%8,%9}, {%0,%1,%2,%3};"
                 : "+f"(d[0]), "+f"(d[1]), "+f"(d[2]), "+f"(d[3])
                 : "r"(a[0]), "r"(a[1]), "r"(a[2]), "r"(a[3]), "r"(b[0]), "r"(b[1]));
}

// ---------- kernel 1: scale + split + pad W (proven layout) ----------
__global__ void prep_W(const float* __restrict__ W) {
    int i = blockIdx.x * blockDim.x + threadIdx.x;
    if (i >= NEXP * DIM) return;
    int e = i >> 11, k = i & (DIM - 1);
    int c = k >> 6, kin = k & 63;
    float x = W[i] * 256.0f;
    __half h = __float2half_rn(x);
    float r = x - __half2float(h);
    __half m = __float2half_rn(r);
    gW[((c * 2 + 0) * NEXP + e) * ROWH + kin] = h;
    gW[((c * 2 + 1) * NEXP + e) * ROWH + kin] = m;
}

// ---------- kernel 2: producer/consumer warp-specialized HMMA GEMM ----------
__global__ __launch_bounds__(THREADS, 1)
void gate_hmma(const float* __restrict__ inp,
               const float* __restrict__ bias,
               float* __restrict__ out,
               int out_size) {
    extern __shared__ __align__(16) char smem[];
    const unsigned SB = smem_u32(smem);
    const unsigned XD = SB + XOFF;
    const unsigned WD = SB + WOFF;
    float* bsm = (float*)(smem + BOFF);

    const int tid  = threadIdx.x;
    const int wid  = tid >> 5;
    const int lane = tid & 31;
    const int tokBase = blockIdx.x * TOKB;

    const bool consumer = (wid < 8);
    const int tg = wid & 3;          // consumer token group (32 tokens each)
    const int kh = (wid >> 2) & 1;   // consumer K half (k32 of each 64-k chunk)

    if (tid < 64) bsm[tid] = bias[tid];

    // consumer fragment base addresses (144B rows, R9-proven lane maps)
    const unsigned aBase = (unsigned)((tg * 32 + (lane & 15)) * 144 + kh * 64 + ((lane >> 4) << 4));
    const unsigned bBase = (unsigned)(((lane & 7) + ((lane >> 4) << 3)) * 144 + kh * 64 + (((lane >> 3) & 1) << 4));

    // producer geometry: warp pw covers tokens pw*16..+15, lane>>4 selects token parity,
    // (lane&15)*16B selects the 16B segment of the 256B chunk row.
    const int pw = wid - 8;
    const float* pSrc = consumer ? nullptr
        : inp + (size_t)(tokBase + pw * 16 + (lane >> 4)) * DIM + (lane & 15) * 4;

    float d0[8][4], d1[8][4];
#pragma unroll
    for (int j = 0; j < 8; j++)
#pragma unroll
        for (int q = 0; q < 4; q++) { d0[j][q] = 0.f; d1[j][q] = 0.f; }

    // ---- producer staging of chunk n into buffer nb ----
    auto produce = [&](int n, int nb) {
        // W: 18432B via cp.async, spread over 256 producer threads
        int p = tid - 256;
#pragma unroll
        for (int j = 0; j < 5; j++) {
            int o = p + j * 256;
            if (o < WBUFB / 16)
                cpasync16(WD + nb * WBUFB + o * 16,
                          (const char*)gW + (size_t)n * WBUFB + o * 16);
        }
        asm volatile("cp.async.commit_group;");
        // X: 16 tokens per warp, fully coalesced LDG (2 tokens x 256B per inst)
        float4 v[8];
#pragma unroll
        for (int i = 0; i < 8; i++)
            v[i] = *(const float4*)(pSrc + (size_t)n * KCH + 2 * i * DIM);
#pragma unroll
        for (int i = 0; i < 8; i++) {
            __half2 h2a = __floats2half2_rn(v[i].x, v[i].y);
            __half2 h2b = __floats2half2_rn(v[i].z, v[i].w);
            float2 fa = __half22float2(h2a);
            float2 fb = __half22float2(h2b);
            __half2 m2a = __floats2half2_rn(v[i].x - fa.x, v[i].y - fa.y);
            __half2 m2b = __floats2half2_rn(v[i].z - fb.x, v[i].w - fb.y);
            ull hull = (ull)(*(unsigned*)&h2a) | ((ull)(*(unsigned*)&h2b) << 32);
            ull mull = (ull)(*(unsigned*)&m2a) | ((ull)(*(unsigned*)&m2b) << 32);
            int t = pw * 16 + 2 * i + (lane >> 4);
            char* xh = smem + XOFF + nb * XBUFB + t * 144 + (lane & 15) * 8;
            *(ull*)xh = hull;
            *(ull*)(xh + XSPLITB) = mull;
        }
        asm volatile("cp.async.wait_group 0;");
    };

    // ---- prologue: producers stage chunk 0 into buf 0 ----
    if (!consumer) produce(0, 0);
    __syncthreads();

    for (int c = 0; c < NCHUNK; c++) {
        const int b = c & 1;
        if (consumer) {
            // ---- compute chunk c: 2 k-steps, waves hh -> mh -> hm ----
            const unsigned xA = XD + b * XBUFB + aBase;
            const unsigned wA = WD + b * WBUFB + bBase;
#pragma unroll
            for (int ks = 0; ks < 2; ks++) {
                const unsigned xk = xA + ks * 32;
                const unsigned wk = wA + ks * 32;
                unsigned ah0[4], ah1[4], am0[4], am1[4];
                unsigned bb[4][4];
                ldm4(ah0, xk);
                ldm4(ah1, xk + 2304);
#pragma unroll
                for (int g = 0; g < 4; g++) ldm4(bb[g], wk + g * 2304);
                // wave 1: hh (16 independent MMAs)
#pragma unroll
                for (int g = 0; g < 4; g++) {
                    mma16816(d0[2*g],   ah0, bb[g]);  mma16816(d0[2*g+1], ah0, bb[g] + 2);
                    mma16816(d1[2*g],   ah1, bb[g]);  mma16816(d1[2*g+1], ah1, bb[g] + 2);
                }
                ldm4(am0, xk + XSPLITB);
                ldm4(am1, xk + XSPLITB + 2304);
                // wave 2: mh
#pragma unroll
                for (int g = 0; g < 4; g++) {
                    mma16816(d0[2*g],   am0, bb[g]);  mma16816(d0[2*g+1], am0, bb[g] + 2);
                    mma16816(d1[2*g],   am1, bb[g]);  mma16816(d1[2*g+1], am1, bb[g] + 2);
                }
                // load bm into bb (bh dead after mh wave)
#pragma unroll
                for (int g = 0; g < 4; g++) ldm4(bb[g], wk + WSPLITB + g * 2304);
                // wave 3: hm
#pragma unroll
                for (int g = 0; g < 4; g++) {
                    mma16816(d0[2*g],   ah0, bb[g]);  mma16816(d0[2*g+1], ah0, bb[g] + 2);
                    mma16816(d1[2*g],   ah1, bb[g]);  mma16816(d1[2*g+1], ah1, bb[g] + 2);
                }
            }
        } else {
            if (c + 1 < NCHUNK) produce(c + 1, (c + 1) & 1);
        }
        __syncthreads();
    }

    // ---- reduce across the 2 K-halves (scratch reuses X staging smem) ----
    float* scr = (float*)smem;   // rows of 68 floats (272B), 128 rows = 34.8KB

    if (consumer && kh == 1) {
        int row = tg * 32 + lane;
#pragma unroll
        for (int j = 0; j < 8; j++)
            *(float4*)(scr + row * 68 + j * 4) = make_float4(d0[j][0], d0[j][1], d0[j][2], d0[j][3]);
#pragma unroll
        for (int j = 0; j < 8; j++)
            *(float4*)(scr + row * 68 + 32 + j * 4) = make_float4(d1[j][0], d1[j][1], d1[j][2], d1[j][3]);
    }
    __syncthreads();

    if (consumer && kh == 0) {
        int row = tg * 32 + lane;
#pragma unroll
        for (int j = 0; j < 8; j++) {
            float4 v = *(const float4*)(scr + row * 68 + j * 4);
            d0[j][0] += v.x; d0[j][1] += v.y; d0[j][2] += v.z; d0[j][3] += v.w;
        }
#pragma unroll
        for (int j = 0; j < 8; j++) {
            float4 v = *(const float4*)(scr + row * 68 + 32 + j * 4);
            d1[j][0] += v.x; d1[j][1] += v.y; d1[j][2] += v.z; d1[j][3] += v.w;
        }

        // ---- epilogue: unscale, +bias, top-2 over 64, softmax ----
        const int half = out_size >> 1;
#pragma unroll
        for (int mt = 0; mt < 2; mt++) {
#pragma unroll
            for (int rh = 0; rh < 2; rh++) {
                float v0 = -3.4e38f, v1 = -3.4e38f;
                int   i0 = -1,       i1 = -1;
#pragma unroll
                for (int j = 0; j < 8; j++) {
#pragma unroll
                    for (int v = 0; v < 2; v++) {
                        int e = j * 8 + (lane & 3) * 2 + v;
                        float dv = (mt == 0) ? d0[j][rh * 2 + v] : d1[j][rh * 2 + v];
                        float f = dv * INV256 + bsm[e];
                        if (f > v0)      { v1 = v0; i1 = i0; v0 = f; i0 = e; }
                        else if (f > v1) { v1 = f;  i1 = e; }
                    }
                }
#pragma unroll
                for (int ofs = 1; ofs < 4; ofs <<= 1) {
                    float u0 = __shfl_xor_sync(0xFFFFFFFFu, v0, ofs);
                    float u1 = __shfl_xor_sync(0xFFFFFFFFu, v1, ofs);
                    int   j0 = __shfl_xor_sync(0xFFFFFFFFu, i0, ofs);
                    int   j1 = __shfl_xor_sync(0xFFFFFFFFu, i1, ofs);
                    bool afirst = (v0 > u0) || (v0 == u0 && i0 < j0);
                    float nv0, nv1; int ni0, ni1;
                    if (afirst) {
                        nv0 = v0; ni0 = i0;
                        bool s = (u0 > v1) || (u0 == v1 && j0 < i1);
                        nv1 = s ? u0 : v1; ni1 = s ? j0 : i1;
                    } else {
                        nv0 = u0; ni0 = j0;
                        bool s = (v0 > u1) || (v0 == u1 && i0 < j1);
                        nv1 = s ? v0 : u1; ni1 = s ? i0 : j1;
                    }
                    v0 = nv0; v1 = nv1; i0 = ni0; i1 = ni1;
                }
                if ((lane & 3) == 0) {
                    int tok = tokBase + tg * 32 + mt * 16 + rh * 8 + (lane >> 2);
                    float ex = expf(v1 - v0);
                    float s0 = 1.0f / (1.0f + ex);
                    float s1 = ex * s0;
                    out[tok * 2 + 0] = (float)i0;
                    out[tok * 2 + 1] = (float)i1;
                    out[half + tok * 2 + 0] = s0;
                    out[half + tok * 2 + 1] = s1;
                }
            }
        }
    }
}

extern "C" void kernel_launch(void* const* d_in, const int* in_sizes, int n_in,
                              void* d_out, int out_size) {
    const float* inp  = (const float*)d_in[0];   // [16384, 2048]
    const float* W    = (const float*)d_in[1];   // [64, 2048]
    const float* bias = (const float*)d_in[2];   // [64]
    float* out = (float*)d_out;

    cudaFuncSetAttribute(gate_hmma, cudaFuncAttributeMaxDynamicSharedMemorySize, SMTOT);
    prep_W<<<(NEXP * DIM + 255) / 256, 256>>>(W);
    gate_hmma<<<NTOK / TOKB, THREADS, SMTOT>>>(inp, bias, out, out_size);
}

// round 14
// speedup vs baseline: 1.3871x; 1.0914x over previous
#include <cuda_runtime.h>
#include <cuda_fp16.h>

#define NTOK 16384
#define NEXP 64
#define DIM  2048
#define KCH  64
#define NCHUNK (DIM / KCH)      // 32
#define TOKB 128
#define THREADS 512
#define ROWH 72                 // 144B rows (72 halfs)
#define XSPLITB (TOKB * 144)    // 18432 B per X split tile
#define XBUFB   (2 * XSPLITB)   // 36864 B per X buffer
#define WSPLITB (64 * 144)      // 9216 B per W split tile
#define WBUFB   (2 * WSPLITB)   // 18432 B per W buffer
// dynamic smem: X 2 bufs, W 2 bufs, bias
#define XOFF 0
#define WOFF (2 * XBUFB)        // 73728
#define BOFF (WOFF + 2 * WBUFB) // 110592
#define SMTOT (BOFF + 256)      // 110848
#define INV256 0.00390625f

typedef unsigned long long ull;

// W pre-scaled x256, fp16 2-split, padded: gW[c][split][exp][ROWH]  (18432B per chunk)
__device__ __align__(16) __half gW[NCHUNK * 2 * NEXP * ROWH];

// ---------- helpers ----------
__device__ __forceinline__ unsigned smem_u32(const void* p) {
    unsigned a;
    asm("{ .reg .u64 t; cvta.to.shared.u64 t, %1; cvt.u32.u64 %0, t; }" : "=r"(a) : "l"(p));
    return a;
}
__device__ __forceinline__ void cpasync16(unsigned s, const void* g) {
    asm volatile("cp.async.cg.shared.global [%0], [%1], 16;" :: "r"(s), "l"(g));
}
__device__ __forceinline__ void ldm4(unsigned* r, unsigned addr) {
    asm volatile("ldmatrix.sync.aligned.m8n8.x4.shared.b16 {%0,%1,%2,%3}, [%4];"
                 : "=r"(r[0]), "=r"(r[1]), "=r"(r[2]), "=r"(r[3]) : "r"(addr));
}
__device__ __forceinline__ void mma16816(float* d, const unsigned* a, const unsigned* b) {
    asm volatile("mma.sync.aligned.m16n8k16.row.col.f32.f16.f16.f32 "
                 "{%0,%1,%2,%3}, {%4,%5,%6,%7}, {%8,%9}, {%0,%1,%2,%3};"
                 : "+f"(d[0]), "+f"(d[1]), "+f"(d[2]), "+f"(d[3])
                 : "r"(a[0]), "r"(a[1]), "r"(a[2]), "r"(a[3]), "r"(b[0]), "r"(b[1]));
}

// ---------- kernel 1: scale + split + pad W (proven layout) ----------
__global__ void prep_W(const float* __restrict__ W) {
    int i = blockIdx.x * blockDim.x + threadIdx.x;
    if (i >= NEXP * DIM) return;
    int e = i >> 11, k = i & (DIM - 1);
    int c = k >> 6, kin = k & 63;
    float x = W[i] * 256.0f;
    __half h = __float2half_rn(x);
    float r = x - __half2float(h);
    __half m = __float2half_rn(r);
    gW[((c * 2 + 0) * NEXP + e) * ROWH + kin] = h;
    gW[((c * 2 + 1) * NEXP + e) * ROWH + kin] = m;
}

// ---------- kernel 2: warp-specialized HMMA GEMM, pipelined producer ----------
__global__ __launch_bounds__(THREADS, 1)
void gate_hmma(const float* __restrict__ inp,
               const float* __restrict__ bias,
               float* __restrict__ out,
               int out_size) {
    extern __shared__ __align__(16) char smem[];
    const unsigned SB = smem_u32(smem);
    const unsigned XD = SB + XOFF;
    const unsigned WD = SB + WOFF;
    float* bsm = (float*)(smem + BOFF);

    const int tid  = threadIdx.x;
    const int wid  = tid >> 5;
    const int lane = tid & 31;
    const int tokBase = blockIdx.x * TOKB;

    const bool consumer = (wid < 8);
    const int tg = wid & 3;          // consumer token group (32 tokens each)
    const int kh = (wid >> 2) & 1;   // consumer K half

    if (tid < 64) bsm[tid] = bias[tid];

    const unsigned aBase = (unsigned)((tg * 32 + (lane & 15)) * 144 + kh * 64 + ((lane >> 4) << 4));
    const unsigned bBase = (unsigned)(((lane & 7) + ((lane >> 4) << 3)) * 144 + kh * 64 + (((lane >> 3) & 1) << 4));

    float d0[8][4], d1[8][4];
#pragma unroll
    for (int j = 0; j < 8; j++)
#pragma unroll
        for (int q = 0; q < 4; q++) { d0[j][q] = 0.f; d1[j][q] = 0.f; }

    if (consumer) {
        // ================= CONSUMER LOOP =================
        __syncthreads();                      // matches producer prologue barrier
        for (int c = 0; c < NCHUNK; c++) {
            const int b = c & 1;
            const unsigned xA = XD + b * XBUFB + aBase;
            const unsigned wA = WD + b * WBUFB + bBase;
#pragma unroll
            for (int ks = 0; ks < 2; ks++) {
                const unsigned xk = xA + ks * 32;
                const unsigned wk = wA + ks * 32;
                unsigned ah0[4], ah1[4], am0[4], am1[4];
                unsigned bb[4][4];
                ldm4(ah0, xk);
                ldm4(ah1, xk + 2304);
#pragma unroll
                for (int g = 0; g < 4; g++) ldm4(bb[g], wk + g * 2304);
                // wave 1: hh
#pragma unroll
                for (int g = 0; g < 4; g++) {
                    mma16816(d0[2*g],   ah0, bb[g]);  mma16816(d0[2*g+1], ah0, bb[g] + 2);
                    mma16816(d1[2*g],   ah1, bb[g]);  mma16816(d1[2*g+1], ah1, bb[g] + 2);
                }
                ldm4(am0, xk + XSPLITB);
                ldm4(am1, xk + XSPLITB + 2304);
                // wave 2: mh
#pragma unroll
                for (int g = 0; g < 4; g++) {
                    mma16816(d0[2*g],   am0, bb[g]);  mma16816(d0[2*g+1], am0, bb[g] + 2);
                    mma16816(d1[2*g],   am1, bb[g]);  mma16816(d1[2*g+1], am1, bb[g] + 2);
                }
#pragma unroll
                for (int g = 0; g < 4; g++) ldm4(bb[g], wk + WSPLITB + g * 2304);
                // wave 3: hm
#pragma unroll
                for (int g = 0; g < 4; g++) {
                    mma16816(d0[2*g],   ah0, bb[g]);  mma16816(d0[2*g+1], ah0, bb[g] + 2);
                    mma16816(d1[2*g],   ah1, bb[g]);  mma16816(d1[2*g+1], ah1, bb[g] + 2);
                }
            }
            __syncthreads();
        }
    } else {
        // ================= PRODUCER LOOP =================
        const int pw = wid - 8;
        const float* pSrc = inp + (size_t)(tokBase + pw * 16 + (lane >> 4)) * DIM + (lane & 15) * 4;

        float4 xr[8];
        auto ldgX = [&](int n) {
#pragma unroll
            for (int i = 0; i < 8; i++)
                xr[i] = *(const float4*)(pSrc + (size_t)n * KCH + 2 * i * DIM);
        };
        auto cpW = [&](int n, int nb) {
            int p = tid - 256;
#pragma unroll
            for (int j = 0; j < 5; j++) {
                int o = p + j * 256;
                if (o < WBUFB / 16)
                    cpasync16(WD + nb * WBUFB + o * 16,
                              (const char*)gW + (size_t)n * WBUFB + o * 16);
            }
            asm volatile("cp.async.commit_group;");
        };
        auto stsX = [&](int nb) {
#pragma unroll
            for (int i = 0; i < 8; i++) {
                __half2 h2a = __floats2half2_rn(xr[i].x, xr[i].y);
                __half2 h2b = __floats2half2_rn(xr[i].z, xr[i].w);
                float2 fa = __half22float2(h2a);
                float2 fb = __half22float2(h2b);
                __half2 m2a = __floats2half2_rn(xr[i].x - fa.x, xr[i].y - fa.y);
                __half2 m2b = __floats2half2_rn(xr[i].z - fb.x, xr[i].w - fb.y);
                ull hull = (ull)(*(unsigned*)&h2a) | ((ull)(*(unsigned*)&h2b) << 32);
                ull mull = (ull)(*(unsigned*)&m2a) | ((ull)(*(unsigned*)&m2b) << 32);
                int t = pw * 16 + 2 * i + (lane >> 4);
                char* xh = smem + XOFF + nb * XBUFB + t * 144 + (lane & 15) * 8;
                *(ull*)xh = hull;
                *(ull*)(xh + XSPLITB) = mull;
            }
        };

        // prologue: stage chunk 0, prefetch X(1)
        ldgX(0);
        cpW(0, 0);
        stsX(0);
        ldgX(1);
        asm volatile("cp.async.wait_group 0;");
        __syncthreads();                      // matches consumer's first barrier

        for (int c = 0; c < NCHUNK; c++) {
            if (c + 1 < NCHUNK) {
                cpW(c + 1, (c + 1) & 1);      // W(c+1): L2-resident, lands within iter
                stsX((c + 1) & 1);            // X(c+1) from prefetched regs
            }
            if (c + 2 < NCHUNK) ldgX(c + 2);  // issue LDG; full iter to land
            asm volatile("cp.async.wait_group 0;");
            __syncthreads();
        }
    }
    __syncthreads();   // all compute done before scratch reuse

    // ---- reduce across the 2 K-halves (scratch reuses X staging smem) ----
    float* scr = (float*)smem;   // rows of 68 floats (272B)

    if (consumer && kh == 1) {
        int row = tg * 32 + lane;
#pragma unroll
        for (int j = 0; j < 8; j++)
            *(float4*)(scr + row * 68 + j * 4) = make_float4(d0[j][0], d0[j][1], d0[j][2], d0[j][3]);
#pragma unroll
        for (int j = 0; j < 8; j++)
            *(float4*)(scr + row * 68 + 32 + j * 4) = make_float4(d1[j][0], d1[j][1], d1[j][2], d1[j][3]);
    }
    __syncthreads();

    if (consumer && kh == 0) {
        int row = tg * 32 + lane;
#pragma unroll
        for (int j = 0; j < 8; j++) {
            float4 v = *(const float4*)(scr + row * 68 + j * 4);
            d0[j][0] += v.x; d0[j][1] += v.y; d0[j][2] += v.z; d0[j][3] += v.w;
        }
#pragma unroll
        for (int j = 0; j < 8; j++) {
            float4 v = *(const float4*)(scr + row * 68 + 32 + j * 4);
            d1[j][0] += v.x; d1[j][1] += v.y; d1[j][2] += v.z; d1[j][3] += v.w;
        }

        // ---- epilogue: unscale, +bias, top-2 over 64, softmax ----
        const int half = out_size >> 1;
#pragma unroll
        for (int mt = 0; mt < 2; mt++) {
#pragma unroll
            for (int rh = 0; rh < 2; rh++) {
                float v0 = -3.4e38f, v1 = -3.4e38f;
                int   i0 = -1,       i1 = -1;
#pragma unroll
                for (int j = 0; j < 8; j++) {
#pragma unroll
                    for (int v = 0; v < 2; v++) {
                        int e = j * 8 + (lane & 3) * 2 + v;
                        float dv = (mt == 0) ? d0[j][rh * 2 + v] : d1[j][rh * 2 + v];
                        float f = dv * INV256 + bsm[e];
                        if (f > v0)      { v1 = v0; i1 = i0; v0 = f; i0 = e; }
                        else if (f > v1) { v1 = f;  i1 = e; }
                    }
                }
#pragma unroll
                for (int ofs = 1; ofs < 4; ofs <<= 1) {
                    float u0 = __shfl_xor_sync(0xFFFFFFFFu, v0, ofs);
                    float u1 = __shfl_xor_sync(0xFFFFFFFFu, v1, ofs);
                    int   j0 = __shfl_xor_sync(0xFFFFFFFFu, i0, ofs);
                    int   j1 = __shfl_xor_sync(0xFFFFFFFFu, i1, ofs);
                    bool afirst = (v0 > u0) || (v0 == u0 && i0 < j0);
                    float nv0, nv1; int ni0, ni1;
                    if (afirst) {
                        nv0 = v0; ni0 = i0;
                        bool s = (u0 > v1) || (u0 == v1 && j0 < i1);
                        nv1 = s ? u0 : v1; ni1 = s ? j0 : i1;
                    } else {
                        nv0 = u0; ni0 = j0;
                        bool s = (v0 > u1) || (v0 == u1 && i0 < j1);
                        nv1 = s ? v0 : u1; ni1 = s ? i0 : j1;
                    }
                    v0 = nv0; v1 = nv1; i0 = ni0; i1 = ni1;
                }
                if ((lane & 3) == 0) {
                    int tok = tokBase + tg * 32 + mt * 16 + rh * 8 + (lane >> 2);
                    float ex = expf(v1 - v0);
                    float s0 = 1.0f / (1.0f + ex);
                    float s1 = ex * s0;
                    out[tok * 2 + 0] = (float)i0;
                    out[tok * 2 + 1] = (float)i1;
                    out[half + tok * 2 + 0] = s0;
                    out[half + tok * 2 + 1] = s1;
                }
            }
        }
    }
}

extern "C" void kernel_launch(void* const* d_in, const int* in_sizes, int n_in,
                              void* d_out, int out_size) {
    const float* inp  = (const float*)d_in[0];   // [16384, 2048]
    const float* W    = (const float*)d_in[1];   // [64, 2048]
    const float* bias = (const float*)d_in[2];   // [64]
    float* out = (float*)d_out;

    cudaFuncSetAttribute(gate_hmma, cudaFuncAttributeMaxDynamicSharedMemorySize, SMTOT);
    prep_W<<<(NEXP * DIM + 255) / 256, 256>>>(W);
    gate_hmma<<<NTOK / TOKB, THREADS, SMTOT>>>(inp, bias, out, out_size);
}